// round 1
// baseline (speedup 1.0000x reference)
#include <cuda_runtime.h>

#define VOCAB 50000
#define EDIM  128
#define HDIM  15
#define G3    45      // 3*HDIM
#define CDIM  20
#define BATCH 512
#define SEQ   512

// Scratch (device globals — allocation inside kernel_launch is forbidden)
__device__ float g_G[(size_t)VOCAB * 48];   // [V][48]: slots 0-15 r, 16-31 z, 32-47 n (col j<15 valid)
__device__ float g_hT[BATCH * 16];          // final hidden, padded to 16
__device__ int   g_is64;                    // token dtype flag

// ---------------------------------------------------------------------------
// Kernel 0: detect whether x is int64 (high words all zero) or int32.
// ---------------------------------------------------------------------------
__global__ void detect_kernel(const int* __restrict__ xi) {
    int ok = 1;
    #pragma unroll
    for (int k = 0; k < 32; ++k)
        if (xi[2 * k + 1] != 0) ok = 0;
    g_is64 = ok;
}

// ---------------------------------------------------------------------------
// Kernel A: G[v][g*16+j] = b_ih[g*15+j] + dot(embed[v], W_ih[g*15+j])
// 4 vocab rows per block, 48 output slots per row.
// ---------------------------------------------------------------------------
__global__ void __launch_bounds__(192) gates_kernel(const float* __restrict__ embed,
                                                    const float* __restrict__ W_ih,
                                                    const float* __restrict__ b_ih) {
    __shared__ __align__(16) float sh[4 * EDIM];
    int v0 = blockIdx.x * 4;
    const float* src = embed + (size_t)v0 * EDIM;
    for (int t = threadIdx.x; t < 4 * EDIM; t += 192) sh[t] = src[t];
    __syncthreads();

    int r    = threadIdx.x / 48;
    int slot = threadIdx.x % 48;
    int g    = slot >> 4;
    int j    = slot & 15;
    float acc = 0.f;
    if (j < 15) {
        int row = g * 15 + j;
        acc = b_ih[row];
        const float4* wp = (const float4*)(W_ih + (size_t)row * EDIM);
        const float4* ep = (const float4*)(sh + r * EDIM);
        #pragma unroll
        for (int k = 0; k < EDIM / 4; ++k) {
            float4 wv = wp[k];
            float4 ev = ep[k];
            acc = fmaf(wv.x, ev.x, acc);
            acc = fmaf(wv.y, ev.y, acc);
            acc = fmaf(wv.z, ev.z, acc);
            acc = fmaf(wv.w, ev.w, acc);
        }
    }
    g_G[(size_t)(v0 + r) * 48 + slot] = acc;
}

// ---------------------------------------------------------------------------
// Kernel B: the GRU recurrence. 16 lanes per batch element, lane j owns h[j].
// W_hh rows in registers; h broadcast via width-16 shuffles; G rows
// software-prefetched 2 steps ahead; token indices loaded in 16-step windows.
// ---------------------------------------------------------------------------
__device__ __forceinline__ float fsig(float x) {
    return __fdividef(1.f, 1.f + __expf(-x));
}
__device__ __forceinline__ float ftanh(float x) {
    float e = __expf(2.f * x);                 // inf/0 at extremes -> correct +-1
    return 1.f - __fdividef(2.f, e + 1.f);
}

__global__ void __launch_bounds__(128) rnn_kernel(const void* __restrict__ xraw,
                                                  const float* __restrict__ W_hh,
                                                  const float* __restrict__ b_hh) {
    const unsigned FULL = 0xffffffffu;
    int gid = (blockIdx.x * blockDim.x + threadIdx.x) >> 4;   // batch element
    int j   = threadIdx.x & 15;
    int jj  = (j < 15) ? j : 14;                               // clamp for loads

    // Per-lane recurrent weights (rows j, 15+j, 30+j of W_hh)
    float wr[15], wz[15], wn[15];
    #pragma unroll
    for (int k = 0; k < 15; ++k) {
        wr[k] = W_hh[jj * 15 + k];
        wz[k] = W_hh[(15 + jj) * 15 + k];
        wn[k] = W_hh[(30 + jj) * 15 + k];
    }
    const float br = b_hh[jj], bz = b_hh[15 + jj], bn = b_hh[30 + jj];

    const long long* xll = (const long long*)xraw;
    const int*       xi  = (const int*)xraw;
    const bool is64 = (g_is64 != 0);
    const size_t base = (size_t)gid * SEQ;

    // Window 0 of token indices (16 per group, one per lane)
    int widx = is64 ? (int)xll[base + j] : xi[base + j];

    const float* Gt = g_G;
    int i0 = __shfl_sync(FULL, widx, 0, 16);
    int i1 = __shfl_sync(FULL, widx, 1, 16);
    float cr = Gt[(size_t)i0 * 48 + j], cz = Gt[(size_t)i0 * 48 + 16 + j], cn = Gt[(size_t)i0 * 48 + 32 + j];
    float nr = Gt[(size_t)i1 * 48 + j], nz = Gt[(size_t)i1 * 48 + 16 + j], nn = Gt[(size_t)i1 * 48 + 32 + j];

    float h = 0.f;
    for (int w = 0; w < SEQ / 16; ++w) {
        int wnext = 0;
        if (w < SEQ / 16 - 1) {
            size_t p = base + (size_t)(w + 1) * 16 + j;
            wnext = is64 ? (int)xll[p] : xi[p];
        }
        #pragma unroll
        for (int i = 0; i < 16; ++i) {
            // prefetch G row for step s+2
            int ip2 = (i < 14) ? __shfl_sync(FULL, widx, i + 2, 16)
                               : __shfl_sync(FULL, wnext, i - 14, 16);
            const float* gp = Gt + (size_t)ip2 * 48;
            float pr = gp[j], pz = gp[16 + j], pn = gp[32 + j];

            // gh = W_hh @ h  (dual accumulators to halve the FMA chain)
            float ar0 = br, ar1 = 0.f, az0 = bz, az1 = 0.f, an0 = bn, an1 = 0.f;
            #pragma unroll
            for (int k = 0; k < 15; ++k) {
                float hk = __shfl_sync(FULL, h, k, 16);
                if (k & 1) {
                    ar1 = fmaf(wr[k], hk, ar1);
                    az1 = fmaf(wz[k], hk, az1);
                    an1 = fmaf(wn[k], hk, an1);
                } else {
                    ar0 = fmaf(wr[k], hk, ar0);
                    az0 = fmaf(wz[k], hk, az0);
                    an0 = fmaf(wn[k], hk, an0);
                }
            }
            float rg = fsig(cr + (ar0 + ar1));
            float zg = fsig(cz + (az0 + az1));
            float ng = ftanh(cn + rg * (an0 + an1));
            h = fmaf(zg, h - ng, ng);          // (1-z)*n + z*h

            cr = nr; cz = nz; cn = nn;
            nr = pr; nz = pz; nn = pn;
        }
        widx = wnext;
    }
    if (j < 15) g_hT[gid * 16 + j] = h;
}

// ---------------------------------------------------------------------------
// Kernel C: logits = hT @ W_out^T + b_out, softmax. One warp per batch row.
// ---------------------------------------------------------------------------
__global__ void __launch_bounds__(256) head_kernel(const float* __restrict__ W_out,
                                                   const float* __restrict__ b_out,
                                                   float* __restrict__ out) {
    const unsigned FULL = 0xffffffffu;
    int b = (blockIdx.x * blockDim.x + threadIdx.x) >> 5;
    int c = threadIdx.x & 31;
    const float* hp = g_hT + b * 16;

    float logit = -1e30f;
    if (c < CDIM) {
        logit = b_out[c];
        #pragma unroll
        for (int k = 0; k < HDIM; ++k)
            logit = fmaf(W_out[c * HDIM + k], hp[k], logit);
    }
    float m = logit;
    #pragma unroll
    for (int o = 16; o > 0; o >>= 1) m = fmaxf(m, __shfl_xor_sync(FULL, m, o));
    float e = (c < CDIM) ? __expf(logit - m) : 0.f;
    float s = e;
    #pragma unroll
    for (int o = 16; o > 0; o >>= 1) s += __shfl_xor_sync(FULL, s, o);
    if (c < CDIM) out[b * CDIM + c] = __fdividef(e, s);
}

// ---------------------------------------------------------------------------
extern "C" void kernel_launch(void* const* d_in, const int* in_sizes, int n_in,
                              void* d_out, int out_size) {
    const void*  x     = d_in[0];                 // [B,S] int64 or int32 (auto-detected)
    const float* embed = (const float*)d_in[1];   // [V,E]
    const float* W_ih  = (const float*)d_in[2];   // [45,E]
    const float* b_ih  = (const float*)d_in[3];   // [45]
    const float* W_hh  = (const float*)d_in[4];   // [45,15]
    const float* b_hh  = (const float*)d_in[5];   // [45]
    const float* W_out = (const float*)d_in[6];   // [20,15]
    const float* b_out = (const float*)d_in[7];   // [20]
    float* out = (float*)d_out;                   // [B,C] float32

    detect_kernel<<<1, 1>>>((const int*)x);
    gates_kernel<<<VOCAB / 4, 192>>>(embed, W_ih, b_ih);
    rnn_kernel<<<(BATCH * 16) / 128, 128>>>(x, W_hh, b_hh);
    head_kernel<<<(BATCH * 32) / 256, 256>>>(W_out, b_out, out);
}

// round 4
// speedup vs baseline: 1.3689x; 1.3689x over previous
#include <cuda_runtime.h>

#define VOCAB 50000
#define EDIM  128
#define HDIM  15
#define CDIM  20
#define BATCH 512
#define SEQ   512

// G table: [v][j] = {gate_r, gate_z, gate_n, unused}  (float4 => one LDG.128/step)
__device__ float4 g_G[(size_t)VOCAB * 16];
__device__ int    g_is64;

__device__ __forceinline__ float tanhap(float x) {
    float y;
    asm("tanh.approx.f32 %0, %1;" : "=f"(y) : "f"(x));
    return y;
}

__device__ __forceinline__ int clampv(int v) {
    return min(max(v, 0), VOCAB - 1);
}

// ---------------------------------------------------------------------------
// Kernel A: G[v][j] = b_ih + embed[v] . W_ih rows  (+ inline int64/int32 detect)
// ---------------------------------------------------------------------------
__global__ void __launch_bounds__(192) gates_kernel(const float* __restrict__ embed,
                                                    const float* __restrict__ W_ih,
                                                    const float* __restrict__ b_ih,
                                                    const int*   __restrict__ xi) {
    if (blockIdx.x == 0 && threadIdx.x == 191) {
        int ok = 1;
        #pragma unroll
        for (int k = 0; k < 32; ++k)
            if (xi[2 * k + 1] != 0) ok = 0;   // int64 tokens < 2^31 => high words zero
        g_is64 = ok;
    }

    __shared__ __align__(16) float sh[4 * EDIM];
    int v0 = blockIdx.x * 4;
    const float* src = embed + (size_t)v0 * EDIM;
    for (int t = threadIdx.x; t < 4 * EDIM; t += 192) sh[t] = src[t];
    __syncthreads();

    int r    = threadIdx.x / 48;
    int slot = threadIdx.x % 48;
    int g    = slot >> 4;
    int j    = slot & 15;
    if (j < 15) {
        int row = g * 15 + j;
        float acc = b_ih[row];
        const float4* wp = (const float4*)(W_ih + (size_t)row * EDIM);
        const float4* ep = (const float4*)(sh + r * EDIM);
        #pragma unroll
        for (int k = 0; k < EDIM / 4; ++k) {
            float4 wv = wp[k];
            float4 ev = ep[k];
            acc = fmaf(wv.x, ev.x, acc);
            acc = fmaf(wv.y, ev.y, acc);
            acc = fmaf(wv.z, ev.z, acc);
            acc = fmaf(wv.w, ev.w, acc);
        }
        ((float*)g_G)[(size_t)(v0 + r) * 64 + j * 4 + g] = acc;
    }
}

// ---------------------------------------------------------------------------
// Kernel B: GRU recurrence + fused classifier head.
// 16 lanes/chain (lane j owns h[j]), 2 chains/warp, 8 warps/block (2/SMSP).
// G rows prefetched 3 steps ahead; token windows prefetched 2 windows ahead.
// ---------------------------------------------------------------------------
__global__ void __launch_bounds__(256) rnn_kernel(const void* __restrict__ xraw,
                                                  const float* __restrict__ W_hh,
                                                  const float* __restrict__ b_hh,
                                                  const float* __restrict__ W_out,
                                                  const float* __restrict__ b_out,
                                                  float* __restrict__ out) {
    const unsigned FULL = 0xffffffffu;
    int gid = blockIdx.x * 16 + (threadIdx.x >> 4);   // batch chain
    int j   = threadIdx.x & 15;
    int jj  = (j < 15) ? j : 14;

    float wr[15], wz[15], wn[15];
    #pragma unroll
    for (int k = 0; k < 15; ++k) {
        wr[k] = W_hh[jj * 15 + k];
        wz[k] = W_hh[(15 + jj) * 15 + k];
        wn[k] = W_hh[(30 + jj) * 15 + k];
    }
    const float br = b_hh[jj], bz = b_hh[15 + jj], bn = b_hh[30 + jj];

    const long long* xll = (const long long*)xraw;
    const int*       xi  = (const int*)xraw;
    const bool is64 = (g_is64 != 0);
    const size_t base = (size_t)gid * SEQ;

    int widx = is64 ? (int)xll[base + j]      : xi[base + j];        // window 0
    int wnxt = is64 ? (int)xll[base + 16 + j] : xi[base + 16 + j];   // window 1

    const float4* G4 = g_G;
    int i0 = clampv(__shfl_sync(FULL, widx, 0, 16));
    int i1 = clampv(__shfl_sync(FULL, widx, 1, 16));
    int i2 = clampv(__shfl_sync(FULL, widx, 2, 16));
    float4 c0 = G4[(size_t)i0 * 16 + j];
    float4 c1 = G4[(size_t)i1 * 16 + j];
    float4 c2 = G4[(size_t)i2 * 16 + j];
    c0.x *= 0.5f; c0.y *= 0.5f;     // pre-halve r,z inputs (sigmoid-via-tanh)
    c1.x *= 0.5f; c1.y *= 0.5f;
    c2.x *= 0.5f; c2.y *= 0.5f;

    float h = 0.f;
    for (int w = 0; w < SEQ / 16; ++w) {
        int wnn = 0;
        if (w < SEQ / 16 - 2) {
            size_t p = base + (size_t)(w + 2) * 16 + j;
            wnn = is64 ? (int)xll[p] : xi[p];
        }
        #pragma unroll 4
        for (int i = 0; i < 16; ++i) {
            // prefetch G row for step s+3 (address path is off the serial chain)
            int li = i + 3;
            int ia = __shfl_sync(FULL, widx, li & 15, 16);
            int ib = __shfl_sync(FULL, wnxt, li & 15, 16);
            int ip = clampv((li < 16) ? ia : ib);
            float4 gnew = G4[(size_t)ip * 16 + j];
            gnew.x *= 0.5f; gnew.y *= 0.5f;

            // gh = W_hh @ h  (dual accumulators)
            float ar0 = br, ar1 = 0.f, az0 = bz, az1 = 0.f, an0 = bn, an1 = 0.f;
            #pragma unroll
            for (int k = 0; k < 15; ++k) {
                float hk = __shfl_sync(FULL, h, k, 16);
                if (k & 1) {
                    ar1 = fmaf(wr[k], hk, ar1);
                    az1 = fmaf(wz[k], hk, az1);
                    an1 = fmaf(wn[k], hk, an1);
                } else {
                    ar0 = fmaf(wr[k], hk, ar0);
                    az0 = fmaf(wz[k], hk, az0);
                    an0 = fmaf(wn[k], hk, an0);
                }
            }
            float rg = fmaf(0.5f, tanhap(fmaf(0.5f, ar0 + ar1, c0.x)), 0.5f);
            float zg = fmaf(0.5f, tanhap(fmaf(0.5f, az0 + az1, c0.y)), 0.5f);
            float ng = tanhap(fmaf(rg, an0 + an1, c0.z));
            h = fmaf(zg, h - ng, ng);        // (1-z)*n + z*h

            c0 = c1; c1 = c2; c2 = gnew;
        }
        widx = wnxt; wnxt = wnn;
    }

    // ---- fused head: logits = W_out @ h + b_out, softmax over 20 classes ----
    float l0 = b_out[j];                                   // class j   (0..15)
    float l1 = (j < 4) ? b_out[16 + j] : -3.0e38f;         // class 16+j
    #pragma unroll
    for (int k = 0; k < 15; ++k) {
        float hk = __shfl_sync(FULL, h, k, 16);
        l0 = fmaf(W_out[j * 15 + k], hk, l0);
        if (j < 4) l1 = fmaf(W_out[(16 + j) * 15 + k], hk, l1);
    }
    float m = fmaxf(l0, l1);
    #pragma unroll
    for (int o = 8; o > 0; o >>= 1) m = fmaxf(m, __shfl_xor_sync(FULL, m, o, 16));
    float e0 = __expf(l0 - m);
    float e1 = (j < 4) ? __expf(l1 - m) : 0.f;
    float s = e0 + e1;
    #pragma unroll
    for (int o = 8; o > 0; o >>= 1) s += __shfl_xor_sync(FULL, s, o, 16);
    float inv = __fdividef(1.f, s);
    out[gid * CDIM + j] = e0 * inv;
    if (j < 4) out[gid * CDIM + 16 + j] = e1 * inv;
}

// ---------------------------------------------------------------------------
extern "C" void kernel_launch(void* const* d_in, const int* in_sizes, int n_in,
                              void* d_out, int out_size) {
    const void*  x     = d_in[0];
    const float* embed = (const float*)d_in[1];
    const float* W_ih  = (const float*)d_in[2];
    const float* b_ih  = (const float*)d_in[3];
    const float* W_hh  = (const float*)d_in[4];
    const float* b_hh  = (const float*)d_in[5];
    const float* W_out = (const float*)d_in[6];
    const float* b_out = (const float*)d_in[7];
    float* out = (float*)d_out;

    gates_kernel<<<VOCAB / 4, 192>>>(embed, W_ih, b_ih, (const int*)x);
    rnn_kernel<<<BATCH / 16, 256>>>(x, W_hh, b_hh, W_out, b_out, out);
}

// round 6
// speedup vs baseline: 3.6144x; 2.6404x over previous
#include <cuda_runtime.h>

#define VOCAB 50000
#define EDIM  128
#define HDIM  15
#define CDIM  20
#define BATCH 512
#define SEQ   512
#define WP    132            // padded W_ih smem pitch (floats)

// G table: [v][j] = {0.5*(r+bhh_r), 0.5*(z+bhh_z), n, 0}
__device__ float4 g_G[(size_t)VOCAB * 16];
__device__ int    g_xi[BATCH * SEQ];     // tokens converted to int32

__device__ __forceinline__ float tanhap(float x) {
    float y;
    asm("tanh.approx.f32 %0, %1;" : "=f"(y) : "f"(x));
    return y;
}
__device__ __forceinline__ int clampv(int v) { return min(max(v, 0), VOCAB - 1); }

// ---------------------------------------------------------------------------
// Kernel 0: convert tokens to int32 (per-block int64/int32 detection).
// ---------------------------------------------------------------------------
__global__ void __launch_bounds__(256) conv_kernel(const void* __restrict__ xraw) {
    __shared__ int s64;
    if (threadIdx.x == 0) {
        const int* xi = (const int*)xraw;
        int ok = 1;
        #pragma unroll
        for (int k = 0; k < 32; ++k)
            if (xi[2 * k + 1] != 0) ok = 0;   // int64 tokens < 2^31 => high words 0
        s64 = ok;
    }
    __syncthreads();
    int i0 = (blockIdx.x * 256 + threadIdx.x) * 4;     // 256 blocks cover 262144
    if (s64) {
        const longlong4 v = ((const longlong4*)xraw)[i0 >> 2];
        int4 o;
        o.x = (int)v.x; o.y = (int)v.y; o.z = (int)v.z; o.w = (int)v.w;
        *(int4*)&g_xi[i0] = o;
    } else {
        *(int4*)&g_xi[i0] = *(const int4*)((const int*)xraw + i0);
    }
}

// ---------------------------------------------------------------------------
// Kernel A: tiled gates GEMM. Block = 256 threads, 64 vocab rows.
// Thread (rr,ss): 4 vocab rows (rr+16i) x hidden unit ss (3 gates).
// W_ih staged in smem (pitch-padded); embed via broadcast LDG (L1-resident).
// ---------------------------------------------------------------------------
__global__ void __launch_bounds__(256) gates_kernel(const float* __restrict__ embed,
                                                    const float* __restrict__ W_ih,
                                                    const float* __restrict__ b_ih,
                                                    const float* __restrict__ b_hh) {
    __shared__ __align__(16) float Wsm[45 * WP];
    for (int i = threadIdx.x; i < 45 * EDIM; i += 256) {
        int r = i >> 7, c = i & 127;
        Wsm[r * WP + c] = W_ih[i];
    }
    __syncthreads();

    int rr = threadIdx.x >> 4;
    int ss = threadIdx.x & 15;
    int sw = min(ss, 14);
    int v0 = blockIdx.x * 64;

    const float4* w0p = (const float4*)&Wsm[sw * WP];
    const float4* w1p = (const float4*)&Wsm[(15 + sw) * WP];
    const float4* w2p = (const float4*)&Wsm[(30 + sw) * WP];

    const float4* ep[4];
    int vr[4];
    #pragma unroll
    for (int i = 0; i < 4; ++i) {
        vr[i] = v0 + rr + 16 * i;
        ep[i] = (const float4*)embed + (size_t)min(vr[i], VOCAB - 1) * 32;
    }

    float ar[4] = {0, 0, 0, 0}, az[4] = {0, 0, 0, 0}, an[4] = {0, 0, 0, 0};
    #pragma unroll 4
    for (int k4 = 0; k4 < 32; ++k4) {
        float4 w0 = w0p[k4], w1 = w1p[k4], w2 = w2p[k4];
        #pragma unroll
        for (int i = 0; i < 4; ++i) {
            float4 a = ep[i][k4];
            ar[i] = fmaf(a.x, w0.x, ar[i]); ar[i] = fmaf(a.y, w0.y, ar[i]);
            ar[i] = fmaf(a.z, w0.z, ar[i]); ar[i] = fmaf(a.w, w0.w, ar[i]);
            az[i] = fmaf(a.x, w1.x, az[i]); az[i] = fmaf(a.y, w1.y, az[i]);
            az[i] = fmaf(a.z, w1.z, az[i]); az[i] = fmaf(a.w, w1.w, az[i]);
            an[i] = fmaf(a.x, w2.x, an[i]); an[i] = fmaf(a.y, w2.y, an[i]);
            an[i] = fmaf(a.z, w2.z, an[i]); an[i] = fmaf(a.w, w2.w, an[i]);
        }
    }

    float bi0 = b_ih[sw] + b_hh[sw];               // fold b_hh into r,z slots
    float bi1 = b_ih[15 + sw] + b_hh[15 + sw];
    float bi2 = b_ih[30 + sw];
    #pragma unroll
    for (int i = 0; i < 4; ++i) {
        if (vr[i] < VOCAB) {
            float4 o;
            o.x = 0.5f * (ar[i] + bi0);            // pre-halved for sigmoid-via-tanh
            o.y = 0.5f * (az[i] + bi1);
            o.z = an[i] + bi2;
            o.w = 0.f;
            if (ss == 15) o = make_float4(0.f, 0.f, 0.f, 0.f);
            g_G[(size_t)vr[i] * 16 + ss] = o;
        }
    }
}

// ---------------------------------------------------------------------------
// Kernel B: GRU recurrence + fused head. 16 lanes/chain, 8 chains/block.
// h exchanged via double-buffered smem (no shfl); G prefetched 3 steps ahead
// with token index read directly from g_xi (broadcast LDG).
// ---------------------------------------------------------------------------
__global__ void __launch_bounds__(128) rnn_kernel(const float* __restrict__ W_hh,
                                                  const float* __restrict__ b_hh,
                                                  const float* __restrict__ W_out,
                                                  const float* __restrict__ b_out,
                                                  float* __restrict__ out) {
    __shared__ __align__(16) float sh[8][2][16];
    const unsigned FULL = 0xffffffffu;
    int chain = threadIdx.x >> 4;
    int j     = threadIdx.x & 15;
    int jj    = min(j, 14);
    int gid   = blockIdx.x * 8 + chain;

    float wr[15], wz[15], wn[15];
    #pragma unroll
    for (int k = 0; k < 15; ++k) {
        wr[k] = 0.5f * W_hh[jj * 15 + k];          // pre-halved (sigmoid-via-tanh)
        wz[k] = 0.5f * W_hh[(15 + jj) * 15 + k];
        wn[k] = W_hh[(30 + jj) * 15 + k];
    }
    const float bn = b_hh[30 + jj];

    const int* xp = g_xi + (size_t)gid * SEQ;
    const float4* G4 = g_G;
    float4 c0 = G4[(size_t)clampv(xp[0]) * 16 + j];
    float4 c1 = G4[(size_t)clampv(xp[1]) * 16 + j];
    float4 c2 = G4[(size_t)clampv(xp[2]) * 16 + j];

    float h = 0.f;
    #pragma unroll 4
    for (int s = 0; s < SEQ; ++s) {
        int pf = (s + 3 < SEQ) ? s + 3 : SEQ - 1;
        float4 gnew = G4[(size_t)clampv(xp[pf]) * 16 + j];

        int p = s & 1;
        sh[chain][p][j] = h;
        __syncwarp(FULL);
        float4 h0 = *(const float4*)&sh[chain][p][0];
        float4 h1 = *(const float4*)&sh[chain][p][4];
        float4 h2 = *(const float4*)&sh[chain][p][8];
        float4 h3 = *(const float4*)&sh[chain][p][12];
        float hh[15] = {h0.x, h0.y, h0.z, h0.w, h1.x, h1.y, h1.z, h1.w,
                        h2.x, h2.y, h2.z, h2.w, h3.x, h3.y, h3.z};

        float ar0 = c0.x, ar1 = 0.f, az0 = c0.y, az1 = 0.f, an0 = bn, an1 = 0.f;
        #pragma unroll
        for (int k = 0; k < 15; ++k) {
            if (k & 1) {
                ar1 = fmaf(wr[k], hh[k], ar1);
                az1 = fmaf(wz[k], hh[k], az1);
                an1 = fmaf(wn[k], hh[k], an1);
            } else {
                ar0 = fmaf(wr[k], hh[k], ar0);
                az0 = fmaf(wz[k], hh[k], az0);
                an0 = fmaf(wn[k], hh[k], an0);
            }
        }
        float rg = fmaf(0.5f, tanhap(ar0 + ar1), 0.5f);
        float zg = fmaf(0.5f, tanhap(az0 + az1), 0.5f);
        float ng = tanhap(fmaf(rg, an0 + an1, c0.z));
        h = fmaf(zg, h - ng, ng);                  // (1-z)*n + z*h

        c0 = c1; c1 = c2; c2 = gnew;
    }

    // ---- fused head: final h exchange + logits + softmax over 20 classes ----
    sh[chain][0][j] = h;
    __syncwarp(FULL);
    float hh[15];
    {
        float4 h0 = *(const float4*)&sh[chain][0][0];
        float4 h1 = *(const float4*)&sh[chain][0][4];
        float4 h2 = *(const float4*)&sh[chain][0][8];
        float4 h3 = *(const float4*)&sh[chain][0][12];
        hh[0]=h0.x; hh[1]=h0.y; hh[2]=h0.z; hh[3]=h0.w;
        hh[4]=h1.x; hh[5]=h1.y; hh[6]=h1.z; hh[7]=h1.w;
        hh[8]=h2.x; hh[9]=h2.y; hh[10]=h2.z; hh[11]=h2.w;
        hh[12]=h3.x; hh[13]=h3.y; hh[14]=h3.z;
    }
    float l0 = b_out[j];
    float l1 = (j < 4) ? b_out[16 + j] : -3.0e38f;
    #pragma unroll
    for (int k = 0; k < 15; ++k) {
        l0 = fmaf(W_out[j * 15 + k], hh[k], l0);
        if (j < 4) l1 = fmaf(W_out[(16 + j) * 15 + k], hh[k], l1);
    }
    float m = fmaxf(l0, l1);
    #pragma unroll
    for (int o = 8; o > 0; o >>= 1) m = fmaxf(m, __shfl_xor_sync(FULL, m, o, 16));
    float e0 = __expf(l0 - m);
    float e1 = (j < 4) ? __expf(l1 - m) : 0.f;
    float sum = e0 + e1;
    #pragma unroll
    for (int o = 8; o > 0; o >>= 1) sum += __shfl_xor_sync(FULL, sum, o, 16);
    float inv = __fdividef(1.f, sum);
    out[gid * CDIM + j] = e0 * inv;
    if (j < 4) out[gid * CDIM + 16 + j] = e1 * inv;
}

// ---------------------------------------------------------------------------
extern "C" void kernel_launch(void* const* d_in, const int* in_sizes, int n_in,
                              void* d_out, int out_size) {
    const void*  x     = d_in[0];
    const float* embed = (const float*)d_in[1];
    const float* W_ih  = (const float*)d_in[2];
    const float* b_ih  = (const float*)d_in[3];
    const float* W_hh  = (const float*)d_in[4];
    const float* b_hh  = (const float*)d_in[5];
    const float* W_out = (const float*)d_in[6];
    const float* b_out = (const float*)d_in[7];
    float* out = (float*)d_out;

    conv_kernel<<<(BATCH * SEQ) / 1024, 256>>>(x);
    gates_kernel<<<(VOCAB + 63) / 64, 256>>>(embed, W_ih, b_ih, b_hh);
    rnn_kernel<<<BATCH / 8, 128>>>(W_hh, b_hh, W_out, b_out, out);
}